// round 16
// baseline (speedup 1.0000x reference)
#include <cuda_runtime.h>
#include <cuda_fp16.h>
#include <math.h>
#include <stdint.h>

// Problem constants
#define B_   4
#define SQ_  2048
#define SK_  4096
#define DDEC 1024
#define DENC 1024
#define H_   16
#define DH_  64
#define R_   256
#define LN_EPS 1e-5f

// Scratch (static device globals — no allocation allowed)
__device__ __half g_q [B_ * SQ_ * (H_ * DH_)];       // Q projected (fp16, pre-scaled 1/8)
__device__ float  g_c [B_ * SK_ * R_];               // latent fp32 (pre-LN)
__device__ __half g_kv[B_ * SK_ * (H_ * 2 * DH_)];   // K|V fp16
__device__ __half g_o [B_ * SQ_ * (H_ * DH_)];       // attn out fp16
// fp16 weights
__device__ __half g_wq  [DDEC * DDEC];
__device__ __half g_wkva[R_ * DENC];
__device__ __half g_wkvb[(H_ * 2 * DH_) * R_];
__device__ __half g_wout[DDEC * (H_ * DH_)];

// ---------------------------------------------------------------------------
// Helpers
// ---------------------------------------------------------------------------
__device__ __forceinline__ uint32_t packh2(float a, float b) {
    __half2 h = __floats2half2_rn(a, b);
    return *reinterpret_cast<uint32_t*>(&h);
}

__device__ __forceinline__ void mma_f16(float* d, const uint32_t* a,
                                        uint32_t b0, uint32_t b1) {
    asm volatile(
        "mma.sync.aligned.m16n8k16.row.col.f32.f16.f16.f32 "
        "{%0,%1,%2,%3}, {%4,%5,%6,%7}, {%8,%9}, {%0,%1,%2,%3};"
        : "+f"(d[0]), "+f"(d[1]), "+f"(d[2]), "+f"(d[3])
        : "r"(a[0]), "r"(a[1]), "r"(a[2]), "r"(a[3]), "r"(b0), "r"(b1));
}

__device__ __forceinline__ void ldm_x2_trans(uint32_t& r0, uint32_t& r1, uint32_t addr) {
    asm volatile("ldmatrix.sync.aligned.m8n8.x2.trans.shared.b16 {%0,%1}, [%2];"
                 : "=r"(r0), "=r"(r1) : "r"(addr));
}

__device__ __forceinline__ uint32_t smem_u32(const void* p) {
    uint32_t a;
    asm("{ .reg .u64 t; cvta.to.shared.u64 t, %1; cvt.u32.u64 %0, t; }"
        : "=r"(a) : "l"(p));
    return a;
}

__device__ __forceinline__ void cpasync16(void* s, const void* g) {
    uint32_t sa = (uint32_t)__cvta_generic_to_shared(s);
    asm volatile("cp.async.cg.shared.global [%0], [%1], 16;" :: "r"(sa), "l"(g));
}
__device__ __forceinline__ void cp_commit() {
    asm volatile("cp.async.commit_group;");
}
template<int N> __device__ __forceinline__ void cp_wait() {
    asm volatile("cp.async.wait_group %0;" :: "n"(N));
}

// ---------------------------------------------------------------------------
// Fused weight convert: all 4 weight tensors in ONE launch.
// ---------------------------------------------------------------------------
__global__ __launch_bounds__(256) void convert_weights_kernel(
    __half* wq, const float* Wq, __half* wkva, const float* Wkva,
    __half* wkvb, const float* Wkvb, __half* wout, const float* Wout)
{
    const int bid = blockIdx.x;
    __half* dst; const float* src; int lb;
    if (bid < 256)      { dst = wq;   src = Wq;   lb = bid; }
    else if (bid < 320) { dst = wkva; src = Wkva; lb = bid - 256; }
    else if (bid < 448) { dst = wkvb; src = Wkvb; lb = bid - 320; }
    else                { dst = wout; src = Wout; lb = bid - 448; }

    const int i0 = lb * 1024 + threadIdx.x;
    float4 v[4];
    #pragma unroll
    for (int u = 0; u < 4; u++) v[u] = ((const float4*)src)[i0 + u * 256];
    #pragma unroll
    for (int u = 0; u < 4; u++) {
        __half2 h0 = __floats2half2_rn(v[u].x, v[u].y);
        __half2 h1 = __floats2half2_rn(v[u].z, v[u].w);
        uint2 uu;
        uu.x = *reinterpret_cast<uint32_t*>(&h0);
        uu.y = *reinterpret_cast<uint32_t*>(&h1);
        ((uint2*)dst)[i0 + u * 256] = uu;
    }
}

// ---------------------------------------------------------------------------
// fp16 tensor-core NT GEMM (round-15: 3-stage, one barrier, 2 CTAs/SM).
// Used for Q-proj (A_F32), c-proj (A_F32), out-proj (fp16 A).
// ---------------------------------------------------------------------------
#define HST 40                          // halfs (fp16 tiles)
#define GST32 40                        // floats (fp32 A tiles)
#define HTILE (128 * HST)               // 5120 halfs  = 10240 B
#define ATILE32 (128 * GST32)           // 5120 floats = 20480 B
#define GEMM_SMEM_F16  (3 * HTILE * 2 + 3 * HTILE * 2)        // 61440 B
#define GEMM_SMEM_AF32 (3 * ATILE32 * 4 + 3 * HTILE * 2)      // 92160 B

template<bool A_F32, bool OUT_HALF>
__global__ __launch_bounds__(256, 2) void gemm_nt_f16_kernel(
    const void* __restrict__ Av, const __half* __restrict__ Bm,
    float* __restrict__ Cf, __half* __restrict__ Ch,
    int M, int N, int K, float escale)
{
    extern __shared__ char smc[];
    float*  As32B = (float*)smc;
    __half* As16B = (__half*)smc;
    __half* BsB   = (__half*)(smc + (A_F32 ? 3 * ATILE32 * 4 : 3 * HTILE * 2));

    const int tid = threadIdx.x;
    const int w   = tid >> 5;
    const int l   = tid & 31;
    const int gr  = l >> 2;
    const int gc  = l & 3;
    const int wm  = w >> 1;
    const int wn  = w & 1;
    const int row0 = blockIdx.y * 128;
    const int col0 = blockIdx.x * 128;

    const float*  A32 = (const float*)Av;
    const __half* A16 = (const __half*)Av;

    float acc[2][8][4];
    #pragma unroll
    for (int mt = 0; mt < 2; mt++)
        #pragma unroll
        for (int nt = 0; nt < 8; nt++)
            #pragma unroll
            for (int k = 0; k < 4; k++) acc[mt][nt][k] = 0.f;

    auto stage = [&](int kt, int buf) {
        if (A_F32) {
            float* As = As32B + buf * ATILE32;
            #pragma unroll
            for (int i = 0; i < 4; i++) {
                int id = tid + i * 256;
                int r  = id >> 3;
                int s  = id & 7;
                cpasync16(&As[r * GST32 + 4 * s],
                          A32 + (size_t)(row0 + r) * K + kt + 4 * s);
            }
        } else {
            __half* As = As16B + buf * HTILE;
            #pragma unroll
            for (int i = 0; i < 2; i++) {
                int id = tid + i * 256;
                int r  = id >> 2;
                int s  = id & 3;
                cpasync16(&As[r * HST + 8 * s],
                          A16 + (size_t)(row0 + r) * K + kt + 8 * s);
            }
        }
        __half* Bs = BsB + buf * HTILE;
        #pragma unroll
        for (int i = 0; i < 2; i++) {
            int id = tid + i * 256;
            int r  = id >> 2;
            int s  = id & 3;
            cpasync16(&Bs[r * HST + 8 * s],
                      Bm + (size_t)(col0 + r) * K + kt + 8 * s);
        }
    };

    const int niter = K / 32;
    stage(0, 0);
    cp_commit();
    if (niter > 1) { stage(32, 1); cp_commit(); }

    int buf = 0;
    for (int it = 0; it < niter; it++) {
        if (it + 1 < niter) cp_wait<1>(); else cp_wait<0>();
        __syncthreads();

        const float*  As32 = As32B + buf * ATILE32;
        const __half* As16 = As16B + buf * HTILE;
        const __half* Bs   = BsB + buf * HTILE;

        #pragma unroll
        for (int ks = 0; ks < 2; ks++) {
            uint32_t a[2][4];
            #pragma unroll
            for (int mt = 0; mt < 2; mt++) {
                const int mr = wm * 32 + mt * 16;
                if (A_F32) {
                    float2 f0 = *(const float2*)&As32[(mr + gr)     * GST32 + 16 * ks + 2 * gc];
                    float2 f1 = *(const float2*)&As32[(mr + gr + 8) * GST32 + 16 * ks + 2 * gc];
                    float2 f2 = *(const float2*)&As32[(mr + gr)     * GST32 + 16 * ks + 8 + 2 * gc];
                    float2 f3 = *(const float2*)&As32[(mr + gr + 8) * GST32 + 16 * ks + 8 + 2 * gc];
                    a[mt][0] = packh2(f0.x, f0.y);
                    a[mt][1] = packh2(f1.x, f1.y);
                    a[mt][2] = packh2(f2.x, f2.y);
                    a[mt][3] = packh2(f3.x, f3.y);
                } else {
                    a[mt][0] = *(const uint32_t*)&As16[(mr + gr)     * HST + 16 * ks + 2 * gc];
                    a[mt][1] = *(const uint32_t*)&As16[(mr + gr + 8) * HST + 16 * ks + 2 * gc];
                    a[mt][2] = *(const uint32_t*)&As16[(mr + gr)     * HST + 16 * ks + 8 + 2 * gc];
                    a[mt][3] = *(const uint32_t*)&As16[(mr + gr + 8) * HST + 16 * ks + 8 + 2 * gc];
                }
            }
            #pragma unroll
            for (int nt = 0; nt < 8; nt++) {
                const int nr = wn * 64 + nt * 8;
                uint32_t b0 = *(const uint32_t*)&Bs[(nr + gr) * HST + 16 * ks + 2 * gc];
                uint32_t b1 = *(const uint32_t*)&Bs[(nr + gr) * HST + 16 * ks + 8 + 2 * gc];
                mma_f16(acc[0][nt], a[0], b0, b1);
                mma_f16(acc[1][nt], a[1], b0, b1);
            }
        }

        if (it + 2 < niter) {
            int nb = buf + 2; if (nb >= 3) nb -= 3;
            stage((it + 2) * 32, nb);
            cp_commit();
        }
        buf = (buf + 1 == 3) ? 0 : buf + 1;
    }

    #pragma unroll
    for (int mt = 0; mt < 2; mt++) {
        #pragma unroll
        for (int nt = 0; nt < 8; nt++) {
            const int r = row0 + wm * 32 + mt * 16 + gr;
            const int c = col0 + wn * 64 + nt * 8 + 2 * gc;
            if (OUT_HALF) {
                __half2 h0 = __floats2half2_rn(acc[mt][nt][0] * escale,
                                               acc[mt][nt][1] * escale);
                __half2 h1 = __floats2half2_rn(acc[mt][nt][2] * escale,
                                               acc[mt][nt][3] * escale);
                *(__half2*)(Ch + (size_t)r * N + c)       = h0;
                *(__half2*)(Ch + (size_t)(r + 8) * N + c) = h1;
            } else {
                *(float2*)(Cf + (size_t)r * N + c) =
                    make_float2(acc[mt][nt][0], acc[mt][nt][1]);
                *(float2*)(Cf + (size_t)(r + 8) * N + c) =
                    make_float2(acc[mt][nt][2], acc[mt][nt][3]);
            }
        }
    }
}

// ---------------------------------------------------------------------------
// LN-fused KV projection: kv[M,2048] = LN(c)[M,256] @ Wkvb[2048,256]^T.
// K = 256 fixed. The CTA's whole A block (128 rows x 256) is LN'd once in a
// pre-pass (warp-per-row, summation order byte-identical to the old LN
// kernel) and written fp16 into a resident smem panel (stride 264 halfs ->
// conflict-free a-frags). Mainloop: B-only 3-stage cp.async staging.
// ---------------------------------------------------------------------------
#define ALNST 264                         // halfs; 132 words % 32 == 4
#define ALN_BYTES (128 * ALNST * 2)       // 67584 B
#define GEMM_SMEM_LN (ALN_BYTES + 3 * HTILE * 2)   // 98304 B

__global__ __launch_bounds__(256, 2) void gemm_ln_kv_kernel(
    const float* __restrict__ Cin, const __half* __restrict__ Bm,
    __half* __restrict__ Ch,
    const float* __restrict__ lng, const float* __restrict__ lnb)
{
    extern __shared__ char smc[];
    __half* As  = (__half*)smc;                       // [128][ALNST]
    __half* BsB = (__half*)(smc + ALN_BYTES);         // 3 x HTILE

    const int tid = threadIdx.x;
    const int w   = tid >> 5;
    const int l   = tid & 31;
    const int gr  = l >> 2;
    const int gc  = l & 3;
    const int wm  = w >> 1;
    const int wn  = w & 1;
    const int row0 = blockIdx.y * 128;
    const int col0 = blockIdx.x * 128;
    const int N = H_ * 2 * DH_;                       // 2048
    const int K = R_;                                 // 256

    auto stageB = [&](int kt, int buf) {
        __half* Bs = BsB + buf * HTILE;
        #pragma unroll
        for (int i = 0; i < 2; i++) {
            int id = tid + i * 256;
            int r  = id >> 2;
            int s  = id & 3;
            cpasync16(&Bs[r * HST + 8 * s],
                      Bm + (size_t)(col0 + r) * K + kt + 8 * s);
        }
    };

    // kick off B tiles 0,1 before the LN pre-pass (loads fly during it)
    stageB(0, 0);
    cp_commit();
    stageB(32, 1);
    cp_commit();

    // LN pre-pass: warp w handles rows w*16 .. w*16+15.
    // Per row: lane l holds cols [4l..4l+3] and [128+4l..128+4l+3] —
    // identical load pattern + shfl order as the old layernorm_kernel.
    const float4* gg = (const float4*)lng;
    const float4* bb = (const float4*)lnb;
    const float4 g0 = gg[l], g1 = gg[l + 32];
    const float4 b0 = bb[l], b1 = bb[l + 32];
    for (int r = 0; r < 16; r++) {
        const int row = w * 16 + r;
        const float4* rp = (const float4*)(Cin + (size_t)(row0 + row) * R_);
        float4 v0 = rp[l];
        float4 v1 = rp[l + 32];

        float s  = v0.x + v0.y + v0.z + v0.w + v1.x + v1.y + v1.z + v1.w;
        float s2 = v0.x * v0.x + v0.y * v0.y + v0.z * v0.z + v0.w * v0.w
                 + v1.x * v1.x + v1.y * v1.y + v1.z * v1.z + v1.w * v1.w;
        #pragma unroll
        for (int o = 16; o > 0; o >>= 1) {
            s  += __shfl_xor_sync(0xFFFFFFFF, s,  o);
            s2 += __shfl_xor_sync(0xFFFFFFFF, s2, o);
        }
        const float mu   = s * (1.f / R_);
        const float var  = s2 * (1.f / R_) - mu * mu;
        const float rstd = rsqrtf(var + LN_EPS);

        uint32_t* ap = (uint32_t*)(As + row * ALNST);
        ap[2 * l]      = packh2((v0.x - mu) * rstd * g0.x + b0.x,
                                (v0.y - mu) * rstd * g0.y + b0.y);
        ap[2 * l + 1]  = packh2((v0.z - mu) * rstd * g0.z + b0.z,
                                (v0.w - mu) * rstd * g0.w + b0.w);
        ap[64 + 2 * l] = packh2((v1.x - mu) * rstd * g1.x + b1.x,
                                (v1.y - mu) * rstd * g1.y + b1.y);
        ap[64 + 2 * l + 1] = packh2((v1.z - mu) * rstd * g1.z + b1.z,
                                    (v1.w - mu) * rstd * g1.w + b1.w);
    }
    __syncthreads();   // A panel ready for all warps

    float acc[2][8][4];
    #pragma unroll
    for (int mt = 0; mt < 2; mt++)
        #pragma unroll
        for (int nt = 0; nt < 8; nt++)
            #pragma unroll
            for (int k = 0; k < 4; k++) acc[mt][nt][k] = 0.f;

    const int niter = K / 32;   // 8
    int buf = 0;
    for (int it = 0; it < niter; it++) {
        if (it + 1 < niter) cp_wait<1>(); else cp_wait<0>();
        __syncthreads();

        const __half* Bs = BsB + buf * HTILE;
        const int kb = it * 32;

        #pragma unroll
        for (int ks = 0; ks < 2; ks++) {
            uint32_t a[2][4];
            #pragma unroll
            for (int mt = 0; mt < 2; mt++) {
                const int mr = wm * 32 + mt * 16;
                const __half* ar0 = As + (mr + gr)     * ALNST + kb + 16 * ks + 2 * gc;
                const __half* ar1 = As + (mr + gr + 8) * ALNST + kb + 16 * ks + 2 * gc;
                a[mt][0] = *(const uint32_t*)(ar0);
                a[mt][1] = *(const uint32_t*)(ar1);
                a[mt][2] = *(const uint32_t*)(ar0 + 8);
                a[mt][3] = *(const uint32_t*)(ar1 + 8);
            }
            #pragma unroll
            for (int nt = 0; nt < 8; nt++) {
                const int nr = wn * 64 + nt * 8;
                uint32_t b0u = *(const uint32_t*)&Bs[(nr + gr) * HST + 16 * ks + 2 * gc];
                uint32_t b1u = *(const uint32_t*)&Bs[(nr + gr) * HST + 16 * ks + 8 + 2 * gc];
                mma_f16(acc[0][nt], a[0], b0u, b1u);
                mma_f16(acc[1][nt], a[1], b0u, b1u);
            }
        }

        if (it + 2 < niter) {
            int nb = buf + 2; if (nb >= 3) nb -= 3;
            stageB((it + 2) * 32, nb);
            cp_commit();
        }
        buf = (buf + 1 == 3) ? 0 : buf + 1;
    }

    #pragma unroll
    for (int mt = 0; mt < 2; mt++) {
        #pragma unroll
        for (int nt = 0; nt < 8; nt++) {
            const int r = row0 + wm * 32 + mt * 16 + gr;
            const int c = col0 + wn * 64 + nt * 8 + 2 * gc;
            __half2 h0 = __floats2half2_rn(acc[mt][nt][0], acc[mt][nt][1]);
            __half2 h1 = __floats2half2_rn(acc[mt][nt][2], acc[mt][nt][3]);
            *(__half2*)(Ch + (size_t)r * N + c)       = h0;
            *(__half2*)(Ch + (size_t)(r + 8) * N + c) = h1;
        }
    }
}

// ---------------------------------------------------------------------------
// fp16 flash attention (m16n8k16), cp.async double-buffered K/V,
// fixed-base softmax. Unchanged.
// ---------------------------------------------------------------------------
#define TQ 128
#define TC 64
#define NCH (SK_ / TC)
#define AST 72
#define AQ_OFF 0
#define K_OFF  (128 * AST)
#define KBUF   (TC * AST)
#define V_OFF  (K_OFF + 2 * KBUF)
#define VBUF   (TC * AST)
#define ATT_SMEM_HALFS (V_OFF + 2 * VBUF)
#define ATT_SMEM_BYTES (ATT_SMEM_HALFS * 2)

__device__ __forceinline__ void stage_kv_f16(
    __half* smh, const __half* src, int pr, int pq, int buf)
{
    __half* kd = smh + K_OFF + buf * KBUF + pr * AST + 16 * pq;
    __half* vd = smh + V_OFF + buf * VBUF + pr * AST + 16 * pq;
    cpasync16(kd,     src + 16 * pq);
    cpasync16(kd + 8, src + 16 * pq + 8);
    cpasync16(vd,     src + DH_ + 16 * pq);
    cpasync16(vd + 8, src + DH_ + 16 * pq + 8);
}

__global__ __launch_bounds__(256) void attention_f16_kernel(
    const __half* __restrict__ q, const __half* __restrict__ kv,
    __half* __restrict__ o)
{
    extern __shared__ __half smh[];
    __half* Qs = smh + AQ_OFF;

    const int tid = threadIdx.x;
    const int w   = tid >> 5;
    const int l   = tid & 31;
    const int gr  = l >> 2;
    const int gc  = l & 3;
    const int q0  = blockIdx.x * TQ;
    const int h   = blockIdx.y;
    const int b   = blockIdx.z;

    const int pr = tid >> 2;
    const int pq = tid & 3;
    const __half* kvb = kv + (size_t)(b * SK_) * (H_ * 2 * DH_) + h * 2 * DH_
                      + (size_t)pr * (H_ * 2 * DH_);
    const size_t chstep = (size_t)TC * (H_ * 2 * DH_);

    #pragma unroll
    for (int i = 0; i < 4; i++) {
        int id = tid + i * 256;
        int r  = id >> 3;
        int s  = id & 7;
        cpasync16(&Qs[r * AST + 8 * s],
                  q + (size_t)(b * SQ_ + q0 + r) * (H_ * DH_) + h * DH_ + 8 * s);
    }
    cp_commit();
    stage_kv_f16(smh, kvb, pr, pq, 0);
    cp_commit();
    stage_kv_f16(smh, kvb + chstep, pr, pq, 1);
    cp_commit();

    cp_wait<2>();
    __syncthreads();

    uint32_t qa[4][4];
    {
        const int qrow = w * 16;
        #pragma unroll
        for (int ks = 0; ks < 4; ks++) {
            qa[ks][0] = *(const uint32_t*)&Qs[(qrow + gr)     * AST + 16 * ks + 2 * gc];
            qa[ks][1] = *(const uint32_t*)&Qs[(qrow + gr + 8) * AST + 16 * ks + 2 * gc];
            qa[ks][2] = *(const uint32_t*)&Qs[(qrow + gr)     * AST + 16 * ks + 8 + 2 * gc];
            qa[ks][3] = *(const uint32_t*)&Qs[(qrow + gr + 8) * AST + 16 * ks + 8 + 2 * gc];
        }
    }

    const uint32_t vbase = smem_u32(smh + V_OFF) + (l & 15) * (AST * 2);

    float l0 = 0.f, l1 = 0.f;
    float oacc[8][4];
    #pragma unroll
    for (int j = 0; j < 8; j++)
        #pragma unroll
        for (int k = 0; k < 4; k++) oacc[j][k] = 0.f;

    for (int t = 0; t < NCH; t++) {
        if (t + 1 < NCH) cp_wait<1>(); else cp_wait<0>();
        __syncthreads();

        const __half* Ks = smh + K_OFF + (t & 1) * KBUF;
        const uint32_t vb = vbase + (t & 1) * (VBUF * 2);

        float sacc[8][4];
        #pragma unroll
        for (int j = 0; j < 8; j++)
            #pragma unroll
            for (int k = 0; k < 4; k++) sacc[j][k] = 0.f;

        #pragma unroll
        for (int j = 0; j < 8; j++) {
            const __half* kr = Ks + (8 * j + gr) * AST + 2 * gc;
            #pragma unroll
            for (int ks = 0; ks < 4; ks++) {
                uint32_t b0 = *(const uint32_t*)(kr + 16 * ks);
                uint32_t b1 = *(const uint32_t*)(kr + 16 * ks + 8);
                mma_f16(sacc[j], qa[ks], b0, b1);
            }
        }

        #pragma unroll
        for (int j = 0; j < 8; j++) {
            sacc[j][0] = __expf(sacc[j][0]);
            sacc[j][1] = __expf(sacc[j][1]);
            sacc[j][2] = __expf(sacc[j][2]);
            sacc[j][3] = __expf(sacc[j][3]);
            l0 += sacc[j][0] + sacc[j][1];
            l1 += sacc[j][2] + sacc[j][3];
        }

        #pragma unroll
        for (int kt = 0; kt < 4; kt++) {
            uint32_t pa[4];
            pa[0] = packh2(sacc[2 * kt][0],     sacc[2 * kt][1]);
            pa[1] = packh2(sacc[2 * kt][2],     sacc[2 * kt][3]);
            pa[2] = packh2(sacc[2 * kt + 1][0], sacc[2 * kt + 1][1]);
            pa[3] = packh2(sacc[2 * kt + 1][2], sacc[2 * kt + 1][3]);
            const uint32_t vrow = vb + kt * (16 * AST * 2);
            #pragma unroll
            for (int jd = 0; jd < 8; jd++) {
                uint32_t b0, b1;
                ldm_x2_trans(b0, b1, vrow + jd * 16);
                mma_f16(oacc[jd], pa, b0, b1);
            }
        }

        __syncthreads();
        if (t + 2 < NCH) {
            stage_kv_f16(smh, kvb + (size_t)(t + 2) * chstep, pr, pq, t & 1);
            cp_commit();
        }
    }

    l0 += __shfl_xor_sync(0xFFFFFFFF, l0, 1);
    l0 += __shfl_xor_sync(0xFFFFFFFF, l0, 2);
    l1 += __shfl_xor_sync(0xFFFFFFFF, l1, 1);
    l1 += __shfl_xor_sync(0xFFFFFFFF, l1, 2);

    float inv0 = 1.f / l0;
    float inv1 = 1.f / l1;
    __half* ob = o + (size_t)(b * SQ_ + q0 + w * 16) * (H_ * DH_) + h * DH_;
    #pragma unroll
    for (int jd = 0; jd < 8; jd++) {
        __half2 v0 = __floats2half2_rn(oacc[jd][0] * inv0, oacc[jd][1] * inv0);
        __half2 v1 = __floats2half2_rn(oacc[jd][2] * inv1, oacc[jd][3] * inv1);
        *(__half2*)(ob + (size_t)gr       * (H_ * DH_) + jd * 8 + 2 * gc) = v0;
        *(__half2*)(ob + (size_t)(gr + 8) * (H_ * DH_) + jd * 8 + 2 * gc) = v1;
    }
}

// ---------------------------------------------------------------------------
// Launch
// ---------------------------------------------------------------------------
extern "C" void kernel_launch(void* const* d_in, const int* in_sizes, int n_in,
                              void* d_out, int out_size)
{
    const float* query = (const float*)d_in[0];
    const float* enc   = (const float*)d_in[1];
    const float* Wq    = (const float*)d_in[2];
    const float* Wkva  = (const float*)d_in[3];
    const float* ln_g  = (const float*)d_in[4];
    const float* ln_b  = (const float*)d_in[5];
    const float* Wkvb  = (const float*)d_in[6];
    const float* Wout  = (const float*)d_in[7];
    float* out = (float*)d_out;

    __half *q, *kv, *o, *wq, *wkva, *wkvb, *wout;
    float *c;
    cudaGetSymbolAddress((void**)&q,    g_q);
    cudaGetSymbolAddress((void**)&c,    g_c);
    cudaGetSymbolAddress((void**)&kv,   g_kv);
    cudaGetSymbolAddress((void**)&o,    g_o);
    cudaGetSymbolAddress((void**)&wq,   g_wq);
    cudaGetSymbolAddress((void**)&wkva, g_wkva);
    cudaGetSymbolAddress((void**)&wkvb, g_wkvb);
    cudaGetSymbolAddress((void**)&wout, g_wout);

    cudaFuncSetAttribute((const void*)gemm_nt_f16_kernel<true, true>,
                         cudaFuncAttributeMaxDynamicSharedMemorySize, GEMM_SMEM_AF32);
    cudaFuncSetAttribute((const void*)gemm_nt_f16_kernel<true, false>,
                         cudaFuncAttributeMaxDynamicSharedMemorySize, GEMM_SMEM_AF32);
    cudaFuncSetAttribute((const void*)gemm_nt_f16_kernel<false, false>,
                         cudaFuncAttributeMaxDynamicSharedMemorySize, GEMM_SMEM_F16);
    cudaFuncSetAttribute((const void*)gemm_ln_kv_kernel,
                         cudaFuncAttributeMaxDynamicSharedMemorySize, GEMM_SMEM_LN);
    cudaFuncSetAttribute((const void*)attention_f16_kernel,
                         cudaFuncAttributeMaxDynamicSharedMemorySize, ATT_SMEM_BYTES);

    // 0) all weight converts in one launch
    convert_weights_kernel<<<704, 256>>>(wq, Wq, wkva, Wkva, wkvb, Wkvb, wout, Wout);

    // 1) Q projection (A = fp32 query, converted in-kernel) -> fp16, pre-scaled 1/8
    gemm_nt_f16_kernel<true, true>
        <<<dim3(DDEC / 128, (B_ * SQ_) / 128), 256, GEMM_SMEM_AF32>>>(
        query, wq, nullptr, q, B_ * SQ_, DDEC, DDEC, 0.125f);

    // 2) Latent projection (A = fp32 encoder_output) -> fp32
    gemm_nt_f16_kernel<true, false>
        <<<dim3(R_ / 128, (B_ * SK_) / 128), 256, GEMM_SMEM_AF32>>>(
        enc, wkva, c, nullptr, B_ * SK_, R_, DENC, 1.f);

    // 3+4) LN-fused KV projection -> fp16 (LayerNorm applied in-kernel)
    gemm_ln_kv_kernel
        <<<dim3((H_ * 2 * DH_) / 128, (B_ * SK_) / 128), 256, GEMM_SMEM_LN>>>(
        c, wkvb, kv, ln_g, ln_b);

    // 5) fp16 flash attention -> fp16
    attention_f16_kernel<<<dim3(SQ_ / TQ, H_, B_), 256, ATT_SMEM_BYTES>>>(q, kv, o);

    // 6) Output projection (A = fp16 attn out) -> fp32
    gemm_nt_f16_kernel<false, false>
        <<<dim3(DDEC / 128, (B_ * SQ_) / 128), 256, GEMM_SMEM_F16>>>(
        o, wout, out, nullptr, B_ * SQ_, DDEC, H_ * DH_, 1.f);
}

// round 17
// speedup vs baseline: 1.0662x; 1.0662x over previous
#include <cuda_runtime.h>
#include <cuda_fp16.h>
#include <math.h>
#include <stdint.h>

// Problem constants
#define B_   4
#define SQ_  2048
#define SK_  4096
#define DDEC 1024
#define DENC 1024
#define H_   16
#define DH_  64
#define R_   256
#define LN_EPS 1e-5f

// Scratch (static device globals — no allocation allowed)
__device__ __half g_q [B_ * SQ_ * (H_ * DH_)];       // Q projected (fp16, pre-scaled 1/8)
__device__ float  g_c [B_ * SK_ * R_];               // latent fp32 (pre-LN)
__device__ __half g_ch[B_ * SK_ * R_];               // latent fp16 (post-LN)
__device__ __half g_kv[B_ * SK_ * (H_ * 2 * DH_)];   // K|V fp16
__device__ __half g_o [B_ * SQ_ * (H_ * DH_)];       // attn out fp16
// fp16 weights
__device__ __half g_wq  [DDEC * DDEC];
__device__ __half g_wkva[R_ * DENC];
__device__ __half g_wkvb[(H_ * 2 * DH_) * R_];
__device__ __half g_wout[DDEC * (H_ * DH_)];

// ---------------------------------------------------------------------------
// Helpers
// ---------------------------------------------------------------------------
__device__ __forceinline__ uint32_t packh2(float a, float b) {
    __half2 h = __floats2half2_rn(a, b);
    return *reinterpret_cast<uint32_t*>(&h);
}

__device__ __forceinline__ void mma_f16(float* d, const uint32_t* a,
                                        uint32_t b0, uint32_t b1) {
    asm volatile(
        "mma.sync.aligned.m16n8k16.row.col.f32.f16.f16.f32 "
        "{%0,%1,%2,%3}, {%4,%5,%6,%7}, {%8,%9}, {%0,%1,%2,%3};"
        : "+f"(d[0]), "+f"(d[1]), "+f"(d[2]), "+f"(d[3])
        : "r"(a[0]), "r"(a[1]), "r"(a[2]), "r"(a[3]), "r"(b0), "r"(b1));
}

__device__ __forceinline__ void ldm_x2_trans(uint32_t& r0, uint32_t& r1, uint32_t addr) {
    asm volatile("ldmatrix.sync.aligned.m8n8.x2.trans.shared.b16 {%0,%1}, [%2];"
                 : "=r"(r0), "=r"(r1) : "r"(addr));
}

__device__ __forceinline__ uint32_t smem_u32(const void* p) {
    uint32_t a;
    asm("{ .reg .u64 t; cvta.to.shared.u64 t, %1; cvt.u32.u64 %0, t; }"
        : "=r"(a) : "l"(p));
    return a;
}

__device__ __forceinline__ void cpasync16(void* s, const void* g) {
    uint32_t sa = (uint32_t)__cvta_generic_to_shared(s);
    asm volatile("cp.async.cg.shared.global [%0], [%1], 16;" :: "r"(sa), "l"(g));
}
__device__ __forceinline__ void cp_commit() {
    asm volatile("cp.async.commit_group;");
}
template<int N> __device__ __forceinline__ void cp_wait() {
    asm volatile("cp.async.wait_group %0;" :: "n"(N));
}

// ---------------------------------------------------------------------------
// Fused weight convert: all 4 weight tensors in ONE launch.
// ---------------------------------------------------------------------------
__global__ __launch_bounds__(256) void convert_weights_kernel(
    __half* wq, const float* Wq, __half* wkva, const float* Wkva,
    __half* wkvb, const float* Wkvb, __half* wout, const float* Wout)
{
    const int bid = blockIdx.x;
    __half* dst; const float* src; int lb;
    if (bid < 256)      { dst = wq;   src = Wq;   lb = bid; }
    else if (bid < 320) { dst = wkva; src = Wkva; lb = bid - 256; }
    else if (bid < 448) { dst = wkvb; src = Wkvb; lb = bid - 320; }
    else                { dst = wout; src = Wout; lb = bid - 448; }

    const int i0 = lb * 1024 + threadIdx.x;
    float4 v[4];
    #pragma unroll
    for (int u = 0; u < 4; u++) v[u] = ((const float4*)src)[i0 + u * 256];
    #pragma unroll
    for (int u = 0; u < 4; u++) {
        __half2 h0 = __floats2half2_rn(v[u].x, v[u].y);
        __half2 h1 = __floats2half2_rn(v[u].z, v[u].w);
        uint2 uu;
        uu.x = *reinterpret_cast<uint32_t*>(&h0);
        uu.y = *reinterpret_cast<uint32_t*>(&h1);
        ((uint2*)dst)[i0 + u * 256] = uu;
    }
}

// ---------------------------------------------------------------------------
// fp16 tensor-core NT GEMM (3-stage, one barrier per iter, 2 CTAs/SM).
// A_F32: A staged raw fp32, converted at frag load (bit-identical rounding).
// OUT_HALF: Ch = half(acc*escale), else Cf = acc.
// ---------------------------------------------------------------------------
#define HST 40                          // halfs (fp16 tiles)
#define GST32 40                        // floats (fp32 A tiles)
#define HTILE (128 * HST)               // 5120 halfs  = 10240 B
#define ATILE32 (128 * GST32)           // 5120 floats = 20480 B
#define GEMM_SMEM_F16  (3 * HTILE * 2 + 3 * HTILE * 2)        // 61440 B
#define GEMM_SMEM_AF32 (3 * ATILE32 * 4 + 3 * HTILE * 2)      // 92160 B

template<bool A_F32, bool OUT_HALF>
__global__ __launch_bounds__(256, 2) void gemm_nt_f16_kernel(
    const void* __restrict__ Av, const __half* __restrict__ Bm,
    float* __restrict__ Cf, __half* __restrict__ Ch,
    int M, int N, int K, float escale)
{
    extern __shared__ char smc[];
    float*  As32B = (float*)smc;
    __half* As16B = (__half*)smc;
    __half* BsB   = (__half*)(smc + (A_F32 ? 3 * ATILE32 * 4 : 3 * HTILE * 2));

    const int tid = threadIdx.x;
    const int w   = tid >> 5;
    const int l   = tid & 31;
    const int gr  = l >> 2;
    const int gc  = l & 3;
    const int wm  = w >> 1;
    const int wn  = w & 1;
    const int row0 = blockIdx.y * 128;
    const int col0 = blockIdx.x * 128;

    const float*  A32 = (const float*)Av;
    const __half* A16 = (const __half*)Av;

    float acc[2][8][4];
    #pragma unroll
    for (int mt = 0; mt < 2; mt++)
        #pragma unroll
        for (int nt = 0; nt < 8; nt++)
            #pragma unroll
            for (int k = 0; k < 4; k++) acc[mt][nt][k] = 0.f;

    auto stage = [&](int kt, int buf) {
        if (A_F32) {
            float* As = As32B + buf * ATILE32;
            #pragma unroll
            for (int i = 0; i < 4; i++) {
                int id = tid + i * 256;
                int r  = id >> 3;
                int s  = id & 7;
                cpasync16(&As[r * GST32 + 4 * s],
                          A32 + (size_t)(row0 + r) * K + kt + 4 * s);
            }
        } else {
            __half* As = As16B + buf * HTILE;
            #pragma unroll
            for (int i = 0; i < 2; i++) {
                int id = tid + i * 256;
                int r  = id >> 2;
                int s  = id & 3;
                cpasync16(&As[r * HST + 8 * s],
                          A16 + (size_t)(row0 + r) * K + kt + 8 * s);
            }
        }
        __half* Bs = BsB + buf * HTILE;
        #pragma unroll
        for (int i = 0; i < 2; i++) {
            int id = tid + i * 256;
            int r  = id >> 2;
            int s  = id & 3;
            cpasync16(&Bs[r * HST + 8 * s],
                      Bm + (size_t)(col0 + r) * K + kt + 8 * s);
        }
    };

    const int niter = K / 32;
    stage(0, 0);
    cp_commit();
    if (niter > 1) { stage(32, 1); cp_commit(); }

    int buf = 0;
    for (int it = 0; it < niter; it++) {
        if (it + 1 < niter) cp_wait<1>(); else cp_wait<0>();
        __syncthreads();

        const float*  As32 = As32B + buf * ATILE32;
        const __half* As16 = As16B + buf * HTILE;
        const __half* Bs   = BsB + buf * HTILE;

        #pragma unroll
        for (int ks = 0; ks < 2; ks++) {
            uint32_t a[2][4];
            #pragma unroll
            for (int mt = 0; mt < 2; mt++) {
                const int mr = wm * 32 + mt * 16;
                if (A_F32) {
                    float2 f0 = *(const float2*)&As32[(mr + gr)     * GST32 + 16 * ks + 2 * gc];
                    float2 f1 = *(const float2*)&As32[(mr + gr + 8) * GST32 + 16 * ks + 2 * gc];
                    float2 f2 = *(const float2*)&As32[(mr + gr)     * GST32 + 16 * ks + 8 + 2 * gc];
                    float2 f3 = *(const float2*)&As32[(mr + gr + 8) * GST32 + 16 * ks + 8 + 2 * gc];
                    a[mt][0] = packh2(f0.x, f0.y);
                    a[mt][1] = packh2(f1.x, f1.y);
                    a[mt][2] = packh2(f2.x, f2.y);
                    a[mt][3] = packh2(f3.x, f3.y);
                } else {
                    a[mt][0] = *(const uint32_t*)&As16[(mr + gr)     * HST + 16 * ks + 2 * gc];
                    a[mt][1] = *(const uint32_t*)&As16[(mr + gr + 8) * HST + 16 * ks + 2 * gc];
                    a[mt][2] = *(const uint32_t*)&As16[(mr + gr)     * HST + 16 * ks + 8 + 2 * gc];
                    a[mt][3] = *(const uint32_t*)&As16[(mr + gr + 8) * HST + 16 * ks + 8 + 2 * gc];
                }
            }
            #pragma unroll
            for (int nt = 0; nt < 8; nt++) {
                const int nr = wn * 64 + nt * 8;
                uint32_t b0 = *(const uint32_t*)&Bs[(nr + gr) * HST + 16 * ks + 2 * gc];
                uint32_t b1 = *(const uint32_t*)&Bs[(nr + gr) * HST + 16 * ks + 8 + 2 * gc];
                mma_f16(acc[0][nt], a[0], b0, b1);
                mma_f16(acc[1][nt], a[1], b0, b1);
            }
        }

        if (it + 2 < niter) {
            int nb = buf + 2; if (nb >= 3) nb -= 3;
            stage((it + 2) * 32, nb);
            cp_commit();
        }
        buf = (buf + 1 == 3) ? 0 : buf + 1;
    }

    #pragma unroll
    for (int mt = 0; mt < 2; mt++) {
        #pragma unroll
        for (int nt = 0; nt < 8; nt++) {
            const int r = row0 + wm * 32 + mt * 16 + gr;
            const int c = col0 + wn * 64 + nt * 8 + 2 * gc;
            if (OUT_HALF) {
                __half2 h0 = __floats2half2_rn(acc[mt][nt][0] * escale,
                                               acc[mt][nt][1] * escale);
                __half2 h1 = __floats2half2_rn(acc[mt][nt][2] * escale,
                                               acc[mt][nt][3] * escale);
                *(__half2*)(Ch + (size_t)r * N + c)       = h0;
                *(__half2*)(Ch + (size_t)(r + 8) * N + c) = h1;
            } else {
                *(float2*)(Cf + (size_t)r * N + c) =
                    make_float2(acc[mt][nt][0], acc[mt][nt][1]);
                *(float2*)(Cf + (size_t)(r + 8) * N + c) =
                    make_float2(acc[mt][nt][2], acc[mt][nt][3]);
            }
        }
    }
}

// ---------------------------------------------------------------------------
// LayerNorm, warp-per-row (8 rows per 256-thr CTA, no CTA barrier).
// ---------------------------------------------------------------------------
__global__ __launch_bounds__(256) void layernorm_kernel(
    const float* __restrict__ c, __half* __restrict__ co,
    const float* __restrict__ g, const float* __restrict__ b)
{
    const int w   = threadIdx.x >> 5;
    const int l   = threadIdx.x & 31;
    const int row = blockIdx.x * 8 + w;

    const float4* rp = (const float4*)(c + (size_t)row * R_);
    float4 v0 = rp[l];
    float4 v1 = rp[l + 32];

    float s  = v0.x + v0.y + v0.z + v0.w + v1.x + v1.y + v1.z + v1.w;
    float s2 = v0.x * v0.x + v0.y * v0.y + v0.z * v0.z + v0.w * v0.w
             + v1.x * v1.x + v1.y * v1.y + v1.z * v1.z + v1.w * v1.w;
    #pragma unroll
    for (int o = 16; o > 0; o >>= 1) {
        s  += __shfl_xor_sync(0xFFFFFFFF, s,  o);
        s2 += __shfl_xor_sync(0xFFFFFFFF, s2, o);
    }
    const float mu   = s * (1.f / R_);
    const float var  = s2 * (1.f / R_) - mu * mu;
    const float rstd = rsqrtf(var + LN_EPS);

    const float4 g0 = ((const float4*)g)[l];
    const float4 g1 = ((const float4*)g)[l + 32];
    const float4 b0 = ((const float4*)b)[l];
    const float4 b1 = ((const float4*)b)[l + 32];

    uint2 o0, o1;
    {
        __half2 ha = __floats2half2_rn((v0.x - mu) * rstd * g0.x + b0.x,
                                       (v0.y - mu) * rstd * g0.y + b0.y);
        __half2 hb = __floats2half2_rn((v0.z - mu) * rstd * g0.z + b0.z,
                                       (v0.w - mu) * rstd * g0.w + b0.w);
        o0.x = *reinterpret_cast<uint32_t*>(&ha);
        o0.y = *reinterpret_cast<uint32_t*>(&hb);
        __half2 hc = __floats2half2_rn((v1.x - mu) * rstd * g1.x + b1.x,
                                       (v1.y - mu) * rstd * g1.y + b1.y);
        __half2 hd = __floats2half2_rn((v1.z - mu) * rstd * g1.z + b1.z,
                                       (v1.w - mu) * rstd * g1.w + b1.w);
        o1.x = *reinterpret_cast<uint32_t*>(&hc);
        o1.y = *reinterpret_cast<uint32_t*>(&hd);
    }
    uint2* op = (uint2*)(co + (size_t)row * R_);
    op[l]      = o0;
    op[l + 32] = o1;
}

// ---------------------------------------------------------------------------
// fp16 flash attention (m16n8k16), 3-buffer cp.async K/V pipeline with ONE
// barrier per chunk (buffer staged at iter t = (t+2)%3 = (t-1)%3, last read
// at iter t-1, which all warps passed at the top-of-loop barrier).
// Fixed-base softmax. Math unchanged from round 13/15.
// ---------------------------------------------------------------------------
#define TQ 128
#define TC 64
#define NCH (SK_ / TC)
#define AST 72
#define AQ_OFF 0
#define K_OFF  (128 * AST)              // 9216 halfs
#define KBUF   (TC * AST)               // 4608
#define V_OFF  (K_OFF + 3 * KBUF)       // 23040
#define VBUF   (TC * AST)
#define ATT_SMEM_HALFS (V_OFF + 3 * VBUF)   // 36864
#define ATT_SMEM_BYTES (ATT_SMEM_HALFS * 2) // 73728 B -> 3 CTAs/SM

__device__ __forceinline__ void stage_kv_f16(
    __half* smh, const __half* src, int pr, int pq, int buf)
{
    __half* kd = smh + K_OFF + buf * KBUF + pr * AST + 16 * pq;
    __half* vd = smh + V_OFF + buf * VBUF + pr * AST + 16 * pq;
    cpasync16(kd,     src + 16 * pq);
    cpasync16(kd + 8, src + 16 * pq + 8);
    cpasync16(vd,     src + DH_ + 16 * pq);
    cpasync16(vd + 8, src + DH_ + 16 * pq + 8);
}

__global__ __launch_bounds__(256) void attention_f16_kernel(
    const __half* __restrict__ q, const __half* __restrict__ kv,
    __half* __restrict__ o)
{
    extern __shared__ __half smh[];
    __half* Qs = smh + AQ_OFF;

    const int tid = threadIdx.x;
    const int w   = tid >> 5;
    const int l   = tid & 31;
    const int gr  = l >> 2;
    const int gc  = l & 3;
    const int q0  = blockIdx.x * TQ;
    const int h   = blockIdx.y;
    const int b   = blockIdx.z;

    const int pr = tid >> 2;
    const int pq = tid & 3;
    const __half* kvb = kv + (size_t)(b * SK_) * (H_ * 2 * DH_) + h * 2 * DH_
                      + (size_t)pr * (H_ * 2 * DH_);
    const size_t chstep = (size_t)TC * (H_ * 2 * DH_);

    // group 1: Q tile
    #pragma unroll
    for (int i = 0; i < 4; i++) {
        int id = tid + i * 256;
        int r  = id >> 3;
        int s  = id & 7;
        cpasync16(&Qs[r * AST + 8 * s],
                  q + (size_t)(b * SQ_ + q0 + r) * (H_ * DH_) + h * DH_ + 8 * s);
    }
    cp_commit();
    // groups 2,3: KV chunks 0,1
    stage_kv_f16(smh, kvb, pr, pq, 0);
    cp_commit();
    stage_kv_f16(smh, kvb + chstep, pr, pq, 1);
    cp_commit();

    cp_wait<2>();                      // Q resident
    __syncthreads();

    uint32_t qa[4][4];
    {
        const int qrow = w * 16;
        #pragma unroll
        for (int ks = 0; ks < 4; ks++) {
            qa[ks][0] = *(const uint32_t*)&Qs[(qrow + gr)     * AST + 16 * ks + 2 * gc];
            qa[ks][1] = *(const uint32_t*)&Qs[(qrow + gr + 8) * AST + 16 * ks + 2 * gc];
            qa[ks][2] = *(const uint32_t*)&Qs[(qrow + gr)     * AST + 16 * ks + 8 + 2 * gc];
            qa[ks][3] = *(const uint32_t*)&Qs[(qrow + gr + 8) * AST + 16 * ks + 8 + 2 * gc];
        }
    }

    const uint32_t vbase = smem_u32(smh + V_OFF) + (l & 15) * (AST * 2);

    float l0 = 0.f, l1 = 0.f;
    float oacc[8][4];
    #pragma unroll
    for (int j = 0; j < 8; j++)
        #pragma unroll
        for (int k = 0; k < 4; k++) oacc[j][k] = 0.f;

    int buf = 0;
    for (int t = 0; t < NCH; t++) {
        if (t + 1 < NCH) cp_wait<1>(); else cp_wait<0>();
        __syncthreads();

        const __half* Ks = smh + K_OFF + buf * KBUF;
        const uint32_t vb = vbase + buf * (VBUF * 2);

        float sacc[8][4];
        #pragma unroll
        for (int j = 0; j < 8; j++)
            #pragma unroll
            for (int k = 0; k < 4; k++) sacc[j][k] = 0.f;

        #pragma unroll
        for (int j = 0; j < 8; j++) {
            const __half* kr = Ks + (8 * j + gr) * AST + 2 * gc;
            #pragma unroll
            for (int ks = 0; ks < 4; ks++) {
                uint32_t b0 = *(const uint32_t*)(kr + 16 * ks);
                uint32_t b1 = *(const uint32_t*)(kr + 16 * ks + 8);
                mma_f16(sacc[j], qa[ks], b0, b1);
            }
        }

        #pragma unroll
        for (int j = 0; j < 8; j++) {
            sacc[j][0] = __expf(sacc[j][0]);
            sacc[j][1] = __expf(sacc[j][1]);
            sacc[j][2] = __expf(sacc[j][2]);
            sacc[j][3] = __expf(sacc[j][3]);
            l0 += sacc[j][0] + sacc[j][1];
            l1 += sacc[j][2] + sacc[j][3];
        }

        #pragma unroll
        for (int kt = 0; kt < 4; kt++) {
            uint32_t pa[4];
            pa[0] = packh2(sacc[2 * kt][0],     sacc[2 * kt][1]);
            pa[1] = packh2(sacc[2 * kt][2],     sacc[2 * kt][3]);
            pa[2] = packh2(sacc[2 * kt + 1][0], sacc[2 * kt + 1][1]);
            pa[3] = packh2(sacc[2 * kt + 1][2], sacc[2 * kt + 1][3]);
            const uint32_t vrow = vb + kt * (16 * AST * 2);
            #pragma unroll
            for (int jd = 0; jd < 8; jd++) {
                uint32_t b0, b1;
                ldm_x2_trans(b0, b1, vrow + jd * 16);
                mma_f16(oacc[jd], pa, b0, b1);
            }
        }

        // stage chunk t+2 into buf (t+2)%3 — no second barrier needed
        if (t + 2 < NCH) {
            int nb = buf + 2; if (nb >= 3) nb -= 3;
            stage_kv_f16(smh, kvb + (size_t)(t + 2) * chstep, pr, pq, nb);
            cp_commit();
        }
        buf = (buf + 1 == 3) ? 0 : buf + 1;
    }

    l0 += __shfl_xor_sync(0xFFFFFFFF, l0, 1);
    l0 += __shfl_xor_sync(0xFFFFFFFF, l0, 2);
    l1 += __shfl_xor_sync(0xFFFFFFFF, l1, 1);
    l1 += __shfl_xor_sync(0xFFFFFFFF, l1, 2);

    float inv0 = 1.f / l0;
    float inv1 = 1.f / l1;
    __half* ob = o + (size_t)(b * SQ_ + q0 + w * 16) * (H_ * DH_) + h * DH_;
    #pragma unroll
    for (int jd = 0; jd < 8; jd++) {
        __half2 v0 = __floats2half2_rn(oacc[jd][0] * inv0, oacc[jd][1] * inv0);
        __half2 v1 = __floats2half2_rn(oacc[jd][2] * inv1, oacc[jd][3] * inv1);
        *(__half2*)(ob + (size_t)gr       * (H_ * DH_) + jd * 8 + 2 * gc) = v0;
        *(__half2*)(ob + (size_t)(gr + 8) * (H_ * DH_) + jd * 8 + 2 * gc) = v1;
    }
}

// ---------------------------------------------------------------------------
// Launch
// ---------------------------------------------------------------------------
extern "C" void kernel_launch(void* const* d_in, const int* in_sizes, int n_in,
                              void* d_out, int out_size)
{
    const float* query = (const float*)d_in[0];
    const float* enc   = (const float*)d_in[1];
    const float* Wq    = (const float*)d_in[2];
    const float* Wkva  = (const float*)d_in[3];
    const float* ln_g  = (const float*)d_in[4];
    const float* ln_b  = (const float*)d_in[5];
    const float* Wkvb  = (const float*)d_in[6];
    const float* Wout  = (const float*)d_in[7];
    float* out = (float*)d_out;

    __half *q, *ch, *kv, *o, *wq, *wkva, *wkvb, *wout;
    float *c;
    cudaGetSymbolAddress((void**)&q,    g_q);
    cudaGetSymbolAddress((void**)&c,    g_c);
    cudaGetSymbolAddress((void**)&ch,   g_ch);
    cudaGetSymbolAddress((void**)&kv,   g_kv);
    cudaGetSymbolAddress((void**)&o,    g_o);
    cudaGetSymbolAddress((void**)&wq,   g_wq);
    cudaGetSymbolAddress((void**)&wkva, g_wkva);
    cudaGetSymbolAddress((void**)&wkvb, g_wkvb);
    cudaGetSymbolAddress((void**)&wout, g_wout);

    cudaFuncSetAttribute((const void*)gemm_nt_f16_kernel<true, true>,
                         cudaFuncAttributeMaxDynamicSharedMemorySize, GEMM_SMEM_AF32);
    cudaFuncSetAttribute((const void*)gemm_nt_f16_kernel<true, false>,
                         cudaFuncAttributeMaxDynamicSharedMemorySize, GEMM_SMEM_AF32);
    cudaFuncSetAttribute((const void*)gemm_nt_f16_kernel<false, true>,
                         cudaFuncAttributeMaxDynamicSharedMemorySize, GEMM_SMEM_F16);
    cudaFuncSetAttribute((const void*)gemm_nt_f16_kernel<false, false>,
                         cudaFuncAttributeMaxDynamicSharedMemorySize, GEMM_SMEM_F16);
    cudaFuncSetAttribute((const void*)attention_f16_kernel,
                         cudaFuncAttributeMaxDynamicSharedMemorySize, ATT_SMEM_BYTES);

    // 0) all weight converts in one launch
    convert_weights_kernel<<<704, 256>>>(wq, Wq, wkva, Wkva, wkvb, Wkvb, wout, Wout);

    // 1) Q projection (A = fp32 query, converted in-kernel) -> fp16, pre-scaled 1/8
    gemm_nt_f16_kernel<true, true>
        <<<dim3(DDEC / 128, (B_ * SQ_) / 128), 256, GEMM_SMEM_AF32>>>(
        query, wq, nullptr, q, B_ * SQ_, DDEC, DDEC, 0.125f);

    // 2) Latent projection (A = fp32 encoder_output) -> fp32
    gemm_nt_f16_kernel<true, false>
        <<<dim3(R_ / 128, (B_ * SK_) / 128), 256, GEMM_SMEM_AF32>>>(
        enc, wkva, c, nullptr, B_ * SK_, R_, DENC, 1.f);

    // 3) LayerNorm fp32 -> fp16 (warp per row)
    layernorm_kernel<<<(B_ * SK_) / 8, 256>>>(c, ch, ln_g, ln_b);

    // 4) KV projection (A = fp16 latent) -> fp16
    gemm_nt_f16_kernel<false, true>
        <<<dim3((H_ * 2 * DH_) / 128, (B_ * SK_) / 128), 256, GEMM_SMEM_F16>>>(
        ch, wkvb, nullptr, kv, B_ * SK_, H_ * 2 * DH_, R_, 1.f);

    // 5) fp16 flash attention -> fp16 (3-buffer single-barrier pipeline)
    attention_f16_kernel<<<dim3(SQ_ / TQ, H_, B_), 256, ATT_SMEM_BYTES>>>(q, kv, o);

    // 6) Output projection (A = fp16 attn out) -> fp32
    gemm_nt_f16_kernel<false, false>
        <<<dim3(DDEC / 128, (B_ * SQ_) / 128), 256, GEMM_SMEM_F16>>>(
        o, wout, out, nullptr, B_ * SQ_, DDEC, H_ * DH_, 1.f);
}